// round 2
// baseline (speedup 1.0000x reference)
#include <cuda_runtime.h>

#define BB 32
#define CC 256
#define NN 4096
#define EE 256
#define NH 8
#define HD 32

// ---------------- scratch (__device__ globals; no allocation allowed) ----------
__device__ float g_mean[BB * CC];           // [b][c]
__device__ float g_wq[BB * CC * NH];        // [b][c][h], pre-scaled by 1/sqrt(HD)
__device__ float g_cbias[BB * NH];          // [b][h], pre-scaled
__device__ float g_attnT[BB * NH * NN];     // [b][h][n] transposed attention
__device__ float g_WvT[CC * EE];            // [c][e]
__device__ float g_xa[BB * NH * CC];        // [b][h][c]

// ---------------- K0: transpose Wv -> WvT --------------------------------------
__global__ void k_wvt(const float* __restrict__ Wv) {
    int c = blockIdx.x;
    int e = threadIdx.x;
    g_WvT[c * EE + e] = Wv[e * CC + c];
}

// ---------------- K1: per-(b,c) spatial mean -----------------------------------
__global__ void k_mean(const float* __restrict__ x) {
    int row = blockIdx.x; // b*CC + c
    const float4* xr = (const float4*)(x + (size_t)row * NN);
    float s = 0.f;
#pragma unroll
    for (int i = 0; i < 4; ++i) {
        float4 v = xr[threadIdx.x + i * 256];
        s += (v.x + v.y) + (v.z + v.w);
    }
#pragma unroll
    for (int m = 16; m; m >>= 1) s += __shfl_xor_sync(0xffffffffu, s, m);
    __shared__ float red[8];
    int wid = threadIdx.x >> 5;
    if ((threadIdx.x & 31) == 0) red[wid] = s;
    __syncthreads();
    if (threadIdx.x == 0) {
        float t = red[0];
#pragma unroll
        for (int w = 1; w < 8; ++w) t += red[w];
        g_mean[row] = t * (1.f / NN);
    }
}

// ---------------- K2: q = mean@Wq^T+bq ; wq_eff = q-folded Wk ------------------
__global__ void k_qk(const float* __restrict__ Wq, const float* __restrict__ bq,
                     const float* __restrict__ Wk, const float* __restrict__ bk) {
    int b = blockIdx.x;
    int tid = threadIdx.x; // 256
    __shared__ float mean_s[CC];
    __shared__ float q_s[EE];
    mean_s[tid] = g_mean[b * CC + tid];
    __syncthreads();
    float acc = bq[tid];
    const float* wr = Wq + (size_t)tid * CC;
    for (int c = 0; c < CC; ++c) acc += mean_s[c] * wr[c];
    q_s[tid] = acc;
    __syncthreads();

    const float invs = 0.17677669529663689f; // 1/sqrt(32)
    int c = tid;
#pragma unroll
    for (int h = 0; h < NH; ++h) {
        float s = 0.f;
#pragma unroll 8
        for (int d = 0; d < HD; ++d)
            s += q_s[h * HD + d] * Wk[(size_t)(h * HD + d) * CC + c]; // coalesced over c
        g_wq[(b * CC + c) * NH + h] = s * invs;
    }
    if (tid < NH) {
        float s = 0.f;
        for (int d = 0; d < HD; ++d) s += q_s[tid * HD + d] * bk[tid * HD + d];
        g_cbias[b * NH + tid] = s * invs;
    }
}

// ---------------- K3: logits[b,n,h] into the attention region of d_out ---------
__global__ void k_logits(const float* __restrict__ x, float* __restrict__ o_attn) {
    int b = blockIdx.y;
    int tid = threadIdx.x; // 128
    __shared__ float wq_s[CC * NH]; // [c][h]
    __shared__ float cb_s[NH];
    for (int i = tid; i < CC * NH; i += 128) wq_s[i] = g_wq[b * CC * NH + i];
    if (tid < NH) cb_s[tid] = g_cbias[b * NH + tid];
    __syncthreads();

    int n0 = blockIdx.x * 512 + tid * 4;
    const float* xb = x + (size_t)b * CC * NN;
    float acc[4][NH];
#pragma unroll
    for (int i = 0; i < 4; ++i)
#pragma unroll
        for (int h = 0; h < NH; ++h) acc[i][h] = 0.f;

    for (int c = 0; c < CC; ++c) {
        float4 xv = *(const float4*)(xb + (size_t)c * NN + n0);
        float4 wa = *(const float4*)(wq_s + c * NH);
        float4 wb = *(const float4*)(wq_s + c * NH + 4);
        float xs[4] = {xv.x, xv.y, xv.z, xv.w};
        float ws[8] = {wa.x, wa.y, wa.z, wa.w, wb.x, wb.y, wb.z, wb.w};
#pragma unroll
        for (int i = 0; i < 4; ++i)
#pragma unroll
            for (int h = 0; h < NH; ++h) acc[i][h] += xs[i] * ws[h];
    }
#pragma unroll
    for (int i = 0; i < 4; ++i) {
        float4 r0, r1;
        r0.x = acc[i][0] + cb_s[0]; r0.y = acc[i][1] + cb_s[1];
        r0.z = acc[i][2] + cb_s[2]; r0.w = acc[i][3] + cb_s[3];
        r1.x = acc[i][4] + cb_s[4]; r1.y = acc[i][5] + cb_s[5];
        r1.z = acc[i][6] + cb_s[6]; r1.w = acc[i][7] + cb_s[7];
        float* dst = o_attn + ((size_t)b * NN + n0 + i) * NH;
        *(float4*)dst = r0;
        *(float4*)(dst + 4) = r1;
    }
}

// ---------------- K4: in-place softmax over n, + attn_T scratch + pos ----------
__device__ __forceinline__ void reduce8(float* v, float* smem, bool domax) {
    int lane = threadIdx.x & 31, wid = threadIdx.x >> 5;
#pragma unroll
    for (int h = 0; h < NH; ++h) {
        float t = v[h];
#pragma unroll
        for (int m = 16; m; m >>= 1) {
            float o = __shfl_xor_sync(0xffffffffu, t, m);
            t = domax ? fmaxf(t, o) : (t + o);
        }
        if (lane == 0) smem[wid * NH + h] = t;
    }
    __syncthreads();
    if (threadIdx.x < NH) {
        float t = smem[threadIdx.x];
        for (int w = 1; w < 16; ++w) {
            float o = smem[w * NH + threadIdx.x];
            t = domax ? fmaxf(t, o) : (t + o);
        }
        smem[threadIdx.x] = t;
    }
    __syncthreads();
#pragma unroll
    for (int h = 0; h < NH; ++h) v[h] = smem[h];
    __syncthreads();
}

__global__ void k_softmax(float* __restrict__ o_attn, float* __restrict__ o_pos) {
    int b = blockIdx.x;
    int tid = threadIdx.x; // 512 threads, 16 warps
    float* ab = o_attn + (size_t)b * NN * NH;
    __shared__ float red[16 * NH];

    float v[8][NH];
#pragma unroll
    for (int k = 0; k < 8; ++k) {
        int n = tid + k * 512;
        const float4* p = (const float4*)(ab + (size_t)n * NH);
        float4 a = p[0], c4 = p[1];
        v[k][0] = a.x;  v[k][1] = a.y;  v[k][2] = a.z;  v[k][3] = a.w;
        v[k][4] = c4.x; v[k][5] = c4.y; v[k][6] = c4.z; v[k][7] = c4.w;
    }
    float mx[NH];
#pragma unroll
    for (int h = 0; h < NH; ++h) mx[h] = v[0][h];
#pragma unroll
    for (int k = 1; k < 8; ++k)
#pragma unroll
        for (int h = 0; h < NH; ++h) mx[h] = fmaxf(mx[h], v[k][h]);
    reduce8(mx, red, true);

    float sm[NH];
#pragma unroll
    for (int h = 0; h < NH; ++h) sm[h] = 0.f;
#pragma unroll
    for (int k = 0; k < 8; ++k)
#pragma unroll
        for (int h = 0; h < NH; ++h) {
            float e = __expf(v[k][h] - mx[h]);
            v[k][h] = e;
            sm[h] += e;
        }
    reduce8(sm, red, false);
    float rz[NH];
#pragma unroll
    for (int h = 0; h < NH; ++h) rz[h] = 1.f / sm[h];

    float px[NH], py[NH];
#pragma unroll
    for (int h = 0; h < NH; ++h) { px[h] = 0.f; py[h] = 0.f; }
#pragma unroll
    for (int k = 0; k < 8; ++k) {
        int n = tid + k * 512;
        float fx = (float)(n >> 6), fy = (float)(n & 63);
#pragma unroll
        for (int h = 0; h < NH; ++h) {
            float a = v[k][h] * rz[h];
            v[k][h] = a;
            px[h] += a * fx;
            py[h] += a * fy;
        }
        float4 r0, r1;
        r0.x = v[k][0]; r0.y = v[k][1]; r0.z = v[k][2]; r0.w = v[k][3];
        r1.x = v[k][4]; r1.y = v[k][5]; r1.z = v[k][6]; r1.w = v[k][7];
        float4* p = (float4*)(ab + (size_t)n * NH);
        p[0] = r0; p[1] = r1;
#pragma unroll
        for (int h = 0; h < NH; ++h)
            g_attnT[((size_t)b * NH + h) * NN + n] = v[k][h]; // coalesced per h
    }
    reduce8(px, red, false);
    reduce8(py, red, false);
    if (tid < NH) {
        o_pos[(b * NH + tid) * 2 + 0] = px[tid];
        o_pos[(b * NH + tid) * 2 + 1] = py[tid];
    }
}

// ---------------- K5: xa[b,h,c] = dot(attn_T[b,h,:], x[b,c,:]) ------------------
__global__ void k_xa(const float* __restrict__ x) {
    int b = blockIdx.y;
    int ct = blockIdx.x;          // 0..7 -> 32 channels each
    int tid = threadIdx.x;        // 256 = 8 warps
    int w = tid >> 5, l = tid & 31;
    int cbase = ct * 32 + w * 4;  // 4 consecutive channels per warp
    __shared__ float a_s[NH * 1024]; // chunk of attn_T: [h][1024 n]
    const float* xb = x + (size_t)b * CC * NN;

    float acc[NH][4];
#pragma unroll
    for (int h = 0; h < NH; ++h)
#pragma unroll
        for (int ci = 0; ci < 4; ++ci) acc[h][ci] = 0.f;

    for (int nc = 0; nc < 4; ++nc) {
        // cooperative stage of the 8x1024 attention chunk
        for (int f = tid; f < 2048; f += 256) {
            int h = f >> 8;
            int n4 = f & 255;
            ((float4*)a_s)[h * 256 + n4] =
                *(const float4*)(g_attnT + ((size_t)b * NH + h) * NN + nc * 1024 + n4 * 4);
        }
        __syncthreads();
#pragma unroll
        for (int j = 0; j < 8; ++j) {
            int n4 = l + j * 32;
            float4 av[NH];
#pragma unroll
            for (int h = 0; h < NH; ++h)
                av[h] = *(const float4*)(a_s + h * 1024 + n4 * 4);
#pragma unroll
            for (int ci = 0; ci < 4; ++ci) {
                float4 xv = *(const float4*)(xb + (size_t)(cbase + ci) * NN + nc * 1024 + n4 * 4);
#pragma unroll
                for (int h = 0; h < NH; ++h)
                    acc[h][ci] += av[h].x * xv.x + av[h].y * xv.y +
                                  av[h].z * xv.z + av[h].w * xv.w;
            }
        }
        __syncthreads();
    }
    // warp reduction, lane 0 writes (static indices only)
#pragma unroll
    for (int h = 0; h < NH; ++h)
#pragma unroll
        for (int ci = 0; ci < 4; ++ci)
#pragma unroll
            for (int m = 16; m; m >>= 1)
                acc[h][ci] += __shfl_down_sync(0xffffffffu, acc[h][ci], m);
    if (l == 0) {
#pragma unroll
        for (int h = 0; h < NH; ++h)
#pragma unroll
            for (int ci = 0; ci < 4; ++ci)
                g_xa[((size_t)b * NH + h) * CC + cbase + ci] = acc[h][ci];
    }
}

// ---------------- K6: values = xa @ Wv^T + bv ; batch ; penalty -----------------
__global__ void k_values(const float* __restrict__ bv, float* __restrict__ o_values,
                         float* __restrict__ o_batch, float* __restrict__ o_pen) {
    int b = blockIdx.x;
    int tid = threadIdx.x; // 256 (= e)
    __shared__ float xa_s[NH * CC];
    for (int i = tid; i < NH * CC; i += 256) xa_s[i] = g_xa[b * NH * CC + i];
    __syncthreads();
    float bve = bv[tid];
    float acc[NH];
#pragma unroll
    for (int h = 0; h < NH; ++h) acc[h] = bve;
    for (int c = 0; c < CC; ++c) {
        float wv = g_WvT[c * EE + tid]; // coalesced over e
#pragma unroll
        for (int h = 0; h < NH; ++h) acc[h] += xa_s[h * CC + c] * wv;
    }
#pragma unroll
    for (int h = 0; h < NH; ++h)
        o_values[((size_t)b * NH + h) * EE + tid] = acc[h];
    if (b == 0) {
        o_batch[tid] = (float)(tid >> 3);
        if (tid == 0) *o_pen = 0.f;
    }
}

// ---------------- launch --------------------------------------------------------
extern "C" void kernel_launch(void* const* d_in, const int* in_sizes, int n_in,
                              void* d_out, int out_size) {
    const float* x  = (const float*)d_in[0];
    const float* Wq = (const float*)d_in[1];
    const float* bq = (const float*)d_in[2];
    const float* Wk = (const float*)d_in[3];
    const float* bk = (const float*)d_in[4];
    const float* Wv = (const float*)d_in[5];
    const float* bv = (const float*)d_in[6];
    (void)in_sizes; (void)n_in; (void)out_size;

    float* out = (float*)d_out;
    float* o_values = out;                          // 32*8*256 = 65536
    float* o_pos    = o_values + BB * NH * EE;      // +512
    float* o_batch  = o_pos + BB * NH * 2;          // +256
    float* o_attn   = o_batch + BB * NH;            // +1048576
    float* o_pen    = o_attn + (size_t)BB * NN * NH; // +1

    k_wvt    <<<256, 256>>>(Wv);
    k_mean   <<<BB * CC, 256>>>(x);
    k_qk     <<<BB, 256>>>(Wq, bq, Wk, bk);
    k_logits <<<dim3(8, BB), 128>>>(x, o_attn);
    k_softmax<<<BB, 512>>>(o_attn, o_pos);
    k_xa     <<<dim3(8, BB), 256>>>(x);
    k_values <<<BB, 256>>>(bv, o_values, o_batch, o_pen);
}

// round 3
// speedup vs baseline: 1.2344x; 1.2344x over previous
#include <cuda_runtime.h>

#define BB 32
#define CC 256
#define NN 4096
#define EE 256
#define NH 8
#define HD 32
#define NCH 8      // n-chunks
#define CHN 512    // n per chunk

// ---------------- scratch ----------------
__device__ float g_mean[BB * CC];
__device__ float g_wq[BB * CC * NH];        // [b][c][h], pre-scaled
__device__ float g_cbias[BB * NH];
__device__ float g_WvT[CC * EE];
__device__ float g_part[BB * NCH * 4 * NH]; // per (b,chunk): m, s, px, py  (each [8])
__device__ float2 g_ms[BB * NH];            // {M, 1/S}
__device__ float g_xap[BB * NCH * CC * NH]; // partial xa per chunk: [c][h]

// ---------------- K0: transpose Wv ----------------
__global__ void k_wvt(const float* __restrict__ Wv) {
    int c = blockIdx.x, e = threadIdx.x;
    g_WvT[c * EE + e] = Wv[e * CC + c];
}

// ---------------- K1: spatial mean ----------------
__global__ void k_mean(const float* __restrict__ x) {
    int row = blockIdx.x;
    const float4* xr = (const float4*)(x + (size_t)row * NN);
    float4 v0 = xr[threadIdx.x];
    float4 v1 = xr[threadIdx.x + 256];
    float4 v2 = xr[threadIdx.x + 512];
    float4 v3 = xr[threadIdx.x + 768];
    float s = ((v0.x + v0.y) + (v0.z + v0.w)) + ((v1.x + v1.y) + (v1.z + v1.w))
            + ((v2.x + v2.y) + (v2.z + v2.w)) + ((v3.x + v3.y) + (v3.z + v3.w));
#pragma unroll
    for (int m = 16; m; m >>= 1) s += __shfl_xor_sync(0xffffffffu, s, m);
    __shared__ float red[8];
    if ((threadIdx.x & 31) == 0) red[threadIdx.x >> 5] = s;
    __syncthreads();
    if (threadIdx.x == 0) {
        float t = red[0];
#pragma unroll
        for (int w = 1; w < 8; ++w) t += red[w];
        g_mean[row] = t * (1.f / NN);
    }
}

// ---------------- K2: q, wq_eff, cbias ----------------
__global__ void k_qk(const float* __restrict__ Wq, const float* __restrict__ bq,
                     const float* __restrict__ Wk, const float* __restrict__ bk) {
    int b = blockIdx.x;
    int tid = threadIdx.x;
    __shared__ float mean_s[CC];
    __shared__ float q_s[EE];
    mean_s[tid] = g_mean[b * CC + tid];
    __syncthreads();
    float acc = bq[tid];
    const float* wr = Wq + (size_t)tid * CC;
#pragma unroll 4
    for (int c = 0; c < CC; ++c) acc += mean_s[c] * wr[c];
    q_s[tid] = acc;
    __syncthreads();

    const float invs = 0.17677669529663689f; // 1/sqrt(32)
    int c = tid;
#pragma unroll
    for (int h = 0; h < NH; ++h) {
        float s = 0.f;
#pragma unroll 8
        for (int d = 0; d < HD; ++d)
            s += q_s[h * HD + d] * Wk[(size_t)(h * HD + d) * CC + c];
        g_wq[(b * CC + c) * NH + h] = s * invs;
    }
    if (tid < NH) {
        float s = 0.f;
        for (int d = 0; d < HD; ++d) s += q_s[tid * HD + d] * bk[tid * HD + d];
        g_cbias[b * NH + tid] = s * invs;
    }
}

// ---------------- K3: logits + per-chunk softmax stats + pos partials ----------
__global__ void __launch_bounds__(256) k_logits(const float* __restrict__ x,
                                                float* __restrict__ o_attn) {
    int b = blockIdx.y, ch = blockIdx.x;
    int tid = threadIdx.x;             // 256 threads
    int half = tid >> 7, nt = tid & 127;

    __shared__ float wq_s[CC * NH];    // 8 KB
    __shared__ float4 red4[8 * 128];   // 16 KB: cross-half partials
    __shared__ float cb_s[NH];
    __shared__ float rs[4 * 24];       // warp partials for s/px/py
    __shared__ float bmax[NH];
    __shared__ float bsum[24];

#pragma unroll
    for (int i = 0; i < 8; ++i) wq_s[tid + i * 256] = g_wq[b * CC * NH + tid + i * 256];
    if (tid < NH) cb_s[tid] = g_cbias[b * NH + tid];
    __syncthreads();

    int n0 = ch * CHN + nt * 4;
    const float* xb = x + (size_t)b * CC * NN;
    float acc[4][NH];
#pragma unroll
    for (int i = 0; i < 4; ++i)
#pragma unroll
        for (int h = 0; h < NH; ++h) acc[i][h] = 0.f;

    int cbase = half * 128;
    for (int c0 = 0; c0 < 128; c0 += 4) {
        float4 xv[4];
#pragma unroll
        for (int u = 0; u < 4; ++u)
            xv[u] = *(const float4*)(xb + (size_t)(cbase + c0 + u) * NN + n0);
#pragma unroll
        for (int u = 0; u < 4; ++u) {
            int c = cbase + c0 + u;
            float4 wa = *(const float4*)(wq_s + c * NH);
            float4 wb = *(const float4*)(wq_s + c * NH + 4);
            float xs[4] = {xv[u].x, xv[u].y, xv[u].z, xv[u].w};
            float ws[8] = {wa.x, wa.y, wa.z, wa.w, wb.x, wb.y, wb.z, wb.w};
#pragma unroll
            for (int i = 0; i < 4; ++i)
#pragma unroll
                for (int h = 0; h < NH; ++h) acc[i][h] += xs[i] * ws[h];
        }
    }

    // cross-half reduce through smem (conflict-free layout [k][nt])
    if (half == 1) {
#pragma unroll
        for (int i = 0; i < 4; ++i) {
            red4[(i * 2 + 0) * 128 + nt] = make_float4(acc[i][0], acc[i][1], acc[i][2], acc[i][3]);
            red4[(i * 2 + 1) * 128 + nt] = make_float4(acc[i][4], acc[i][5], acc[i][6], acc[i][7]);
        }
    }
    __syncthreads();

    float v[4][NH];
    if (half == 0) {
#pragma unroll
        for (int i = 0; i < 4; ++i) {
            float4 r0 = red4[(i * 2 + 0) * 128 + nt];
            float4 r1 = red4[(i * 2 + 1) * 128 + nt];
            v[i][0] = acc[i][0] + r0.x + cb_s[0]; v[i][1] = acc[i][1] + r0.y + cb_s[1];
            v[i][2] = acc[i][2] + r0.z + cb_s[2]; v[i][3] = acc[i][3] + r0.w + cb_s[3];
            v[i][4] = acc[i][4] + r1.x + cb_s[4]; v[i][5] = acc[i][5] + r1.y + cb_s[5];
            v[i][6] = acc[i][6] + r1.z + cb_s[6]; v[i][7] = acc[i][7] + r1.w + cb_s[7];
            // store logits
            float* dst = o_attn + ((size_t)b * NN + n0 + i) * NH;
            *(float4*)dst = make_float4(v[i][0], v[i][1], v[i][2], v[i][3]);
            *(float4*)(dst + 4) = make_float4(v[i][4], v[i][5], v[i][6], v[i][7]);
        }
        // per-thread max over 4 n's
        float tm[NH];
#pragma unroll
        for (int h = 0; h < NH; ++h)
            tm[h] = fmaxf(fmaxf(v[0][h], v[1][h]), fmaxf(v[2][h], v[3][h]));
        // warp max
#pragma unroll
        for (int h = 0; h < NH; ++h)
#pragma unroll
            for (int m = 16; m; m >>= 1)
                tm[h] = fmaxf(tm[h], __shfl_xor_sync(0xffffffffu, tm[h], m));
        int w = nt >> 5;
        if ((nt & 31) == 0)
#pragma unroll
            for (int h = 0; h < NH; ++h) rs[w * 24 + h] = tm[h];
    }
    __syncthreads();
    if (tid < NH)
        bmax[tid] = fmaxf(fmaxf(rs[tid], rs[24 + tid]), fmaxf(rs[48 + tid], rs[72 + tid]));
    __syncthreads();

    if (half == 0) {
        float mloc[NH], s[NH], px[NH], py[NH];
#pragma unroll
        for (int h = 0; h < NH; ++h) { mloc[h] = bmax[h]; s[h] = 0.f; px[h] = 0.f; py[h] = 0.f; }
#pragma unroll
        for (int i = 0; i < 4; ++i) {
            int n = n0 + i;
            float fx = (float)(n >> 6), fy = (float)(n & 63);
#pragma unroll
            for (int h = 0; h < NH; ++h) {
                float e = __expf(v[i][h] - mloc[h]);
                s[h] += e; px[h] += e * fx; py[h] += e * fy;
            }
        }
        float r[24];
#pragma unroll
        for (int h = 0; h < NH; ++h) { r[h] = s[h]; r[8 + h] = px[h]; r[16 + h] = py[h]; }
#pragma unroll
        for (int k = 0; k < 24; ++k)
#pragma unroll
            for (int m = 16; m; m >>= 1) r[k] += __shfl_xor_sync(0xffffffffu, r[k], m);
        int w = nt >> 5;
        if ((nt & 31) == 0)
#pragma unroll
            for (int k = 0; k < 24; ++k) rs[w * 24 + k] = r[k];
    }
    __syncthreads();
    if (tid < 24)
        bsum[tid] = rs[tid] + rs[24 + tid] + rs[48 + tid] + rs[72 + tid];
    __syncthreads();
    if (tid < NH) {
        float* gp = g_part + ((size_t)b * NCH + ch) * 32;
        gp[tid]      = bmax[tid];
        gp[8 + tid]  = bsum[tid];        // s
        gp[16 + tid] = bsum[8 + tid];    // px
        gp[24 + tid] = bsum[16 + tid];   // py
    }
}

// ---------------- K4: combine chunk stats -> M, 1/S, pos ----------------
__global__ void k_combine(float* __restrict__ o_pos) {
    int t = threadIdx.x;          // 256 = (b, h)
    int b = t >> 3, h = t & 7;
    const float* gp = g_part + (size_t)b * NCH * 32;
    float M = -3.4e38f;
#pragma unroll
    for (int ch = 0; ch < NCH; ++ch) M = fmaxf(M, gp[ch * 32 + h]);
    float S = 0.f, PX = 0.f, PY = 0.f;
#pragma unroll
    for (int ch = 0; ch < NCH; ++ch) {
        float e = __expf(gp[ch * 32 + h] - M);
        S  += gp[ch * 32 + 8 + h] * e;
        PX += gp[ch * 32 + 16 + h] * e;
        PY += gp[ch * 32 + 24 + h] * e;
    }
    float invS = 1.f / S;
    o_pos[t * 2 + 0] = PX * invS;
    o_pos[t * 2 + 1] = PY * invS;
    g_ms[t] = make_float2(M, invS);
}

// ---------------- K5: apply softmax (write attention) + partial xa -------------
__global__ void __launch_bounds__(256) k_xa(const float* __restrict__ x,
                                            float* __restrict__ o_attn) {
    int b = blockIdx.y, ch = blockIdx.x;
    int tid = threadIdx.x;        // 256 = 8 warps
    int w = tid >> 5, l = tid & 31;
    __shared__ float a_s[NH * CHN];   // [h][n] 16 KB
    __shared__ float2 ms_s[NH];
    if (tid < NH) ms_s[tid] = g_ms[b * NH + tid];
    __syncthreads();

    // stage 1: load logits, apply exp, write attention, stash transposed in smem
    float* ab = o_attn + ((size_t)b * NN + ch * CHN) * NH;
    {
        int nl = tid * 2;  // 2 n per thread
        float4 p[4];
#pragma unroll
        for (int k = 0; k < 4; ++k) p[k] = *(const float4*)(ab + nl * NH + k * 4);
        float av[16];
        av[0]=p[0].x; av[1]=p[0].y; av[2]=p[0].z; av[3]=p[0].w;
        av[4]=p[1].x; av[5]=p[1].y; av[6]=p[1].z; av[7]=p[1].w;
        av[8]=p[2].x; av[9]=p[2].y; av[10]=p[2].z; av[11]=p[2].w;
        av[12]=p[3].x; av[13]=p[3].y; av[14]=p[3].z; av[15]=p[3].w;
#pragma unroll
        for (int k = 0; k < 16; ++k) {
            int h = k & 7;
            av[k] = __expf(av[k] - ms_s[h].x) * ms_s[h].y;
        }
#pragma unroll
        for (int k = 0; k < 4; ++k)
            *(float4*)(ab + nl * NH + k * 4) =
                make_float4(av[k*4], av[k*4+1], av[k*4+2], av[k*4+3]);
#pragma unroll
        for (int k = 0; k < 16; ++k) {
            int h = k & 7, dn = k >> 3;
            a_s[h * CHN + nl + dn] = av[k];
        }
    }
    __syncthreads();

    // stage 2: partial xa over this n-chunk for all 256 channels
    const float* xb = x + (size_t)b * CC * NN + ch * CHN;
    float* xp = g_xap + ((size_t)b * NCH + ch) * CC * NH;
#pragma unroll 1
    for (int cc = 0; cc < 8; ++cc) {
        int c0 = cc * 32 + w * 4;
        float acc[NH][4];
#pragma unroll
        for (int h = 0; h < NH; ++h)
#pragma unroll
            for (int ci = 0; ci < 4; ++ci) acc[h][ci] = 0.f;
#pragma unroll
        for (int j = 0; j < 4; ++j) {
            int nn = l * 4 + j * 128;
            float4 av[NH];
#pragma unroll
            for (int h = 0; h < NH; ++h) av[h] = *(const float4*)(a_s + h * CHN + nn);
#pragma unroll
            for (int ci = 0; ci < 4; ++ci) {
                float4 xv = *(const float4*)(xb + (size_t)(c0 + ci) * NN + nn);
#pragma unroll
                for (int h = 0; h < NH; ++h)
                    acc[h][ci] += av[h].x * xv.x + av[h].y * xv.y +
                                  av[h].z * xv.z + av[h].w * xv.w;
            }
        }
#pragma unroll
        for (int h = 0; h < NH; ++h)
#pragma unroll
            for (int ci = 0; ci < 4; ++ci)
#pragma unroll
                for (int m = 16; m; m >>= 1)
                    acc[h][ci] += __shfl_down_sync(0xffffffffu, acc[h][ci], m);
        if (l == 0) {
#pragma unroll
            for (int ci = 0; ci < 4; ++ci)
#pragma unroll
                for (int h = 0; h < NH; ++h)
                    xp[(c0 + ci) * NH + h] = acc[h][ci];
        }
    }
}

// ---------------- K6: reduce xa partials, values GEMM, batch, penalty ----------
__global__ void k_values(const float* __restrict__ bv, float* __restrict__ o_values,
                         float* __restrict__ o_batch, float* __restrict__ o_pen) {
    int b = blockIdx.x;
    int tid = threadIdx.x;   // 256
    __shared__ float xa_s[CC * NH];  // [c][h]
#pragma unroll
    for (int i = 0; i < 8; ++i) {
        int idx = i * 256 + tid;
        float s = 0.f;
#pragma unroll
        for (int ch = 0; ch < NCH; ++ch)
            s += g_xap[((size_t)b * NCH + ch) * CC * NH + idx];
        xa_s[idx] = s;
    }
    __syncthreads();
    float bve = bv[tid];
    float acc[NH];
#pragma unroll
    for (int h = 0; h < NH; ++h) acc[h] = bve;
#pragma unroll 4
    for (int c = 0; c < CC; ++c) {
        float wv = g_WvT[c * EE + tid];
#pragma unroll
        for (int h = 0; h < NH; ++h) acc[h] += xa_s[c * NH + h] * wv;
    }
#pragma unroll
    for (int h = 0; h < NH; ++h)
        o_values[((size_t)b * NH + h) * EE + tid] = acc[h];
    if (b == 0) {
        o_batch[tid] = (float)(tid >> 3);
        if (tid == 0) *o_pen = 0.f;
    }
}

// ---------------- launch ----------------
extern "C" void kernel_launch(void* const* d_in, const int* in_sizes, int n_in,
                              void* d_out, int out_size) {
    const float* x  = (const float*)d_in[0];
    const float* Wq = (const float*)d_in[1];
    const float* bq = (const float*)d_in[2];
    const float* Wk = (const float*)d_in[3];
    const float* bk = (const float*)d_in[4];
    const float* Wv = (const float*)d_in[5];
    const float* bv = (const float*)d_in[6];
    (void)in_sizes; (void)n_in; (void)out_size;

    float* out = (float*)d_out;
    float* o_values = out;                           // 65536
    float* o_pos    = o_values + BB * NH * EE;       // +512
    float* o_batch  = o_pos + BB * NH * 2;           // +256
    float* o_attn   = o_batch + BB * NH;             // +1048576
    float* o_pen    = o_attn + (size_t)BB * NN * NH; // +1

    k_wvt    <<<256, 256>>>(Wv);
    k_mean   <<<BB * CC, 256>>>(x);
    k_qk     <<<BB, 256>>>(Wq, bq, Wk, bk);
    k_logits <<<dim3(NCH, BB), 256>>>(x, o_attn);
    k_combine<<<1, 256>>>(o_pos);
    k_xa     <<<dim3(NCH, BB), 256>>>(x, o_attn);
    k_values <<<BB, 256>>>(bv, o_values, o_batch, o_pen);
}